// round 7
// baseline (speedup 1.0000x reference)
#include <cuda_runtime.h>
#include <math.h>

#define BB 32
#define NN 300
#define TT 12
#define DD 64
#define MM 16
#define BT (BB*TT)        // 384
#define ND (NN*DD)        // 19200
#define NN2 (NN*NN)       // 90000
#define KPAD 320
#define NPAD 320

// ---- scratch (device globals; no runtime allocation) ----
__device__ float g_S[NN2];             // alpha1@alpha2
__device__ float g_Bm[NN2];            // beta1@beta2
__device__ float g_W[NN*DD*DD];        // per-node weights [N,64,64]
__device__ float g_gcnWT4[192*DD];     // gcnW rearranged
__device__ float g_At[(size_t)BT*KPAD*NPAD]; // A transposed [bt][k(320)][n(320)] ~157MB
__device__ float g_Xp[(size_t)BT*ND];  // X transposed [bt][n][d]
__device__ float g_H1[(size_t)BT*ND];
__device__ float g_H2[(size_t)BT*ND];
__device__ float g_Tmp[(size_t)BT*ND];

// ---- packed fp32x2 helpers (SASS FFMA2 path) ----
typedef unsigned long long u64;
__device__ __forceinline__ void fma2(u64 &d, u64 a, u64 b) {
    asm("fma.rn.f32x2 %0, %1, %2, %3;" : "=l"(d) : "l"(a), "l"(b), "l"(d));
}
__device__ __forceinline__ u64 rep2(float x) {
    u64 r; unsigned int u = __float_as_uint(x);
    asm("mov.b64 %0, {%1,%1};" : "=l"(r) : "r"(u));
    return r;
}
__device__ __forceinline__ float lo2(u64 v) { return __uint_as_float((unsigned)v); }
__device__ __forceinline__ float hi2(u64 v) { return __uint_as_float((unsigned)(v >> 32)); }
__device__ __forceinline__ float gcomp(u64 v, int lane) { return lane ? hi2(v) : lo2(v); }

// gated residual: sigmoid(x)*tanh(x) == (1-e^-x)/(1+e^-2x)
__device__ __forceinline__ float gated(float p) {
    float pc = fminf(fmaxf(p, -20.f), 20.f);
    float u = __expf(-pc);
    return __fdividef(1.f - u, 1.f + u*u);
}

// ---------------- tiny precompute kernels ----------------
__global__ void k_SB(const float* __restrict__ a1, const float* __restrict__ a2,
                     const float* __restrict__ b1, const float* __restrict__ b2) {
    int idx = blockIdx.x*256 + threadIdx.x;
    if (idx >= NN2) return;
    int i = idx / NN, k = idx % NN;
    float s = 0.f, bm = 0.f;
#pragma unroll
    for (int m = 0; m < MM; m++) {
        s  += a1[i*MM+m] * a2[m*NN+k];
        bm += b1[i*MM+m] * b2[m*NN+k];
    }
    g_S[idx] = s; g_Bm[idx] = bm;
}

__global__ void k_Wp(const float* __restrict__ w1, const float* __restrict__ w2) {
    int idx = blockIdx.x*256 + threadIdx.x;
    if (idx >= NN*DD*DD) return;
    int n = idx / (DD*DD), r = idx % (DD*DD);
    float s = 0.f;
#pragma unroll
    for (int m = 0; m < MM; m++) s += w1[n*MM+m] * w2[m*DD*DD+r];
    g_W[idx] = s;
}

__global__ void k_gWT(const float* __restrict__ gcnW) {
    int idx = blockIdx.x*256 + threadIdx.x;
    if (idx >= 192*DD) return;
    int i  = idx & 3;
    int d  = (idx >> 2) & 63;
    int f4 = idx >> 8;
    g_gcnWT4[idx] = gcnW[d*192 + f4*4 + i];
}

// transpose X[b,d,n,t] -> Xp[bt][n][d]
__global__ void k_txp(const float* __restrict__ X) {
    int n = blockIdx.x, b = blockIdx.y;
    __shared__ float tile[DD][13];
    int tid = threadIdx.x;
#pragma unroll
    for (int i = 0; i < 3; i++) {
        int lin = tid + i*256;
        if (lin < DD*TT) {
            int d = lin / TT, t = lin % TT;
            tile[d][t] = X[(((size_t)b*DD+d)*NN+n)*TT + t];
        }
    }
    __syncthreads();
#pragma unroll
    for (int i = 0; i < 3; i++) {
        int lin = tid + i*256;
        if (lin < DD*TT) {
            int t = lin >> 6, d = lin & 63;
            g_Xp[(size_t)(b*TT+t)*ND + n*DD + d] = tile[d][t];
        }
    }
}

// ---------------- adjacency: At[bt][col][row] = relu(S*sin(te@adjW^T+adjB)+Bm)^T ----
// M-tile 64 rows(n) x 64 cols(k-of-mm), 128 threads, 4x8 micro, prefetch
__global__ void __launch_bounds__(128) k_adj(const float* __restrict__ te,
                                             const float* __restrict__ adjW,
                                             const float* __restrict__ adjB) {
    const int bt = blockIdx.y;
    const int b = bt / TT, t = bt % TT;
    const int rt = blockIdx.x % 5;
    const int ct = blockIdx.x / 5;
    const int rowBase = rt*64, colBase = ct*64;
    __shared__ __align__(16) float As_t[32][68];   // [kk][row]
    __shared__ __align__(16) float Bs[32][68];     // [kk][col]
    const int tid = threadIdx.x;
    const int tx = tid & 7, ty = tid >> 3;
    // staging ids: 2 threads per row/col, 16 k each
    const int sr = tid >> 1, sh = tid & 1;
    const int arow = rowBase + sr;
    const int bcol = colBase + sr;
    u64 acc[2][8] = {};
    float4 aR[4], bR[4];

    // prefetch chunk 0
    {
        const float* ap = te + (((size_t)b*NN + arow)*TT + t)*DD + sh*16;
        const float* bp = adjW + (size_t)bcol*DD + sh*16;
#pragma unroll
        for (int c = 0; c < 4; c++) {
            aR[c] = (arow < NN) ? *(const float4*)(ap + 4*c) : make_float4(0,0,0,0);
            bR[c] = (bcol < NN) ? *(const float4*)(bp + 4*c) : make_float4(0,0,0,0);
        }
    }
#pragma unroll
    for (int ch = 0; ch < 2; ch++) {
#pragma unroll
        for (int c = 0; c < 4; c++) {
            As_t[sh*16+4*c+0][sr] = aR[c].x; As_t[sh*16+4*c+1][sr] = aR[c].y;
            As_t[sh*16+4*c+2][sr] = aR[c].z; As_t[sh*16+4*c+3][sr] = aR[c].w;
            Bs [sh*16+4*c+0][sr] = bR[c].x; Bs [sh*16+4*c+1][sr] = bR[c].y;
            Bs [sh*16+4*c+2][sr] = bR[c].z; Bs [sh*16+4*c+3][sr] = bR[c].w;
        }
        __syncthreads();
        if (ch == 0) {
            const float* ap = te + (((size_t)b*NN + arow)*TT + t)*DD + 32 + sh*16;
            const float* bp = adjW + (size_t)bcol*DD + 32 + sh*16;
#pragma unroll
            for (int c = 0; c < 4; c++) {
                aR[c] = (arow < NN) ? *(const float4*)(ap + 4*c) : make_float4(0,0,0,0);
                bR[c] = (bcol < NN) ? *(const float4*)(bp + 4*c) : make_float4(0,0,0,0);
            }
        }
#pragma unroll 8
        for (int kk = 0; kk < 32; kk++) {
            ulonglong2 ap2 = *(const ulonglong2*)&As_t[kk][ty*4];
            float4 b0 = *(const float4*)&Bs[kk][tx*8];
            float4 b1 = *(const float4*)&Bs[kk][tx*8+4];
            u64 apx[2] = {ap2.x, ap2.y};
            u64 br[8] = {rep2(b0.x),rep2(b0.y),rep2(b0.z),rep2(b0.w),
                         rep2(b1.x),rep2(b1.y),rep2(b1.z),rep2(b1.w)};
#pragma unroll
            for (int i = 0; i < 2; i++)
#pragma unroll
                for (int j = 0; j < 8; j++)
                    fma2(acc[i][j], apx[i], br[j]);
        }
        __syncthreads();
    }

    // epilogue: sin/scale/relu, write transposed At[col][row], zero for col>=NN
    float* Atb = g_At + (size_t)bt*KPAD*NPAD;
#pragma unroll
    for (int j = 0; j < 8; j++) {
        int col = colBase + tx*8 + j;
        int cc = col < NN ? col : 0;
        float bias = adjB[cc];
        float o[4];
#pragma unroll
        for (int e = 0; e < 4; e++) {
            int row = rowBase + ty*4 + e;
            int rc = row < NN ? row : 0;
            float v = 0.f;
            if (col < NN) {
                float pre = gcomp(acc[e>>1][j], e&1);
                v = __sinf(pre + bias);
                v = g_S[rc*NN+cc]*v + g_Bm[rc*NN+cc];
                v = v > 0.f ? v : 0.f;
            }
            o[e] = v;
        }
        *(float4*)(Atb + (size_t)col*NPAD + rowBase + ty*4) =
            make_float4(o[0], o[1], o[2], o[3]);
    }
}

// ---------------- Tmp = A @ Hb  (At[k][n] staged directly) ----------------
__global__ void __launch_bounds__(128) k_mm(int hop) {
    const int bt = blockIdx.y;
    const int rowBase = blockIdx.x*64;
    const float* Hbt = ((hop == 0) ? g_Xp : g_H1) + (size_t)bt*ND;
    const float* Atb = g_At + (size_t)bt*KPAD*NPAD;
    __shared__ __align__(16) float As_t[32][68];   // [kk][row]
    __shared__ __align__(16) float Bs[32][68];     // [kk][d]
    const int tid = threadIdx.x;
    const int tx = tid & 7, ty = tid >> 3;
    const int skk = tid >> 2, sq = tid & 3;        // staging: 4 float4 per thread
    u64 acc[2][8] = {};
    float4 aR[4], bR[4];

    // prefetch chunk 0
    {
        const float* ap = Atb + (size_t)skk*NPAD + rowBase + sq*16;
        const float* bp = Hbt + (size_t)skk*DD + sq*16;
#pragma unroll
        for (int c = 0; c < 4; c++) {
            aR[c] = *(const float4*)(ap + 4*c);
            bR[c] = *(const float4*)(bp + 4*c);
        }
    }
#pragma unroll 2
    for (int ch = 0; ch < 10; ch++) {
#pragma unroll
        for (int c = 0; c < 4; c++) {
            *(float4*)&As_t[skk][sq*16+4*c] = aR[c];
            *(float4*)&Bs[skk][sq*16+4*c]  = bR[c];
        }
        __syncthreads();
        if (ch < 9) {
            int k0 = (ch+1)*32;
            const float* ap = Atb + (size_t)(k0+skk)*NPAD + rowBase + sq*16;
            const float* bp = Hbt + (size_t)(k0+skk)*DD + sq*16;
            bool bv = (k0 + skk) < NN;
#pragma unroll
            for (int c = 0; c < 4; c++) {
                aR[c] = *(const float4*)(ap + 4*c);   // padded zeros for k>=300
                bR[c] = bv ? *(const float4*)(bp + 4*c) : make_float4(0,0,0,0);
            }
        }
#pragma unroll 8
        for (int kk = 0; kk < 32; kk++) {
            ulonglong2 ap2 = *(const ulonglong2*)&As_t[kk][ty*4];
            float4 b0 = *(const float4*)&Bs[kk][tx*8];
            float4 b1 = *(const float4*)&Bs[kk][tx*8+4];
            u64 apx[2] = {ap2.x, ap2.y};
            u64 br[8] = {rep2(b0.x),rep2(b0.y),rep2(b0.z),rep2(b0.w),
                         rep2(b1.x),rep2(b1.y),rep2(b1.z),rep2(b1.w)};
#pragma unroll
            for (int i = 0; i < 2; i++)
#pragma unroll
                for (int j = 0; j < 8; j++)
                    fma2(acc[i][j], apx[i], br[j]);
        }
        __syncthreads();
    }

    float* Tbt = g_Tmp + (size_t)bt*ND;
    const int c0 = tx*8;
#pragma unroll
    for (int i = 0; i < 2; i++) {
#pragma unroll
        for (int lane = 0; lane < 2; lane++) {
            int row = rowBase + ty*4 + 2*i + lane;
            if (row >= NN) continue;
            float* tp = Tbt + (size_t)row*DD + c0;
            *(float4*)tp = make_float4(gcomp(acc[i][0],lane), gcomp(acc[i][1],lane),
                                       gcomp(acc[i][2],lane), gcomp(acc[i][3],lane));
            *(float4*)(tp+4) = make_float4(gcomp(acc[i][4],lane), gcomp(acc[i][5],lane),
                                           gcomp(acc[i][6],lane), gcomp(acc[i][7],lane));
        }
    }
}

// ---------------- per-node matmul + gated residual ----------------
// rows = 64 bt (grid.x: 6 tiles, all valid), cols = 64 d, K = 64, W[n] as B
__global__ void __launch_bounds__(128) k_nodemm(int hop) {
    const int n = blockIdx.y;
    const int rowBase = blockIdx.x*64;
    float* Hout = (hop == 0) ? g_H1 : g_H2;
    const float* Wn = g_W + (size_t)n*DD*DD;
    __shared__ __align__(16) float As_t[32][68];   // [kk][btRow]
    __shared__ __align__(16) float Bs[32][68];     // [kk][d]
    const int tid = threadIdx.x;
    const int tx = tid & 7, ty = tid >> 3;
    const int sr = tid >> 1, sh = tid & 1;         // A staging: 2 thr/row
    const int skk = tid >> 2, sq = tid & 3;        // B staging
    u64 acc[2][8] = {};
    float4 aR[4], bR[4];

    {
        const float* ap = g_Tmp + (size_t)(rowBase + sr)*ND + n*DD + sh*16;
        const float* bp = Wn + (size_t)skk*DD + sq*16;
#pragma unroll
        for (int c = 0; c < 4; c++) {
            aR[c] = *(const float4*)(ap + 4*c);
            bR[c] = *(const float4*)(bp + 4*c);
        }
    }
#pragma unroll
    for (int ch = 0; ch < 2; ch++) {
#pragma unroll
        for (int c = 0; c < 4; c++) {
            As_t[sh*16+4*c+0][sr] = aR[c].x; As_t[sh*16+4*c+1][sr] = aR[c].y;
            As_t[sh*16+4*c+2][sr] = aR[c].z; As_t[sh*16+4*c+3][sr] = aR[c].w;
            *(float4*)&Bs[skk][sq*16+4*c] = bR[c];
        }
        __syncthreads();
        if (ch == 0) {
            const float* ap = g_Tmp + (size_t)(rowBase + sr)*ND + n*DD + 32 + sh*16;
            const float* bp = Wn + (size_t)(32+skk)*DD + sq*16;
#pragma unroll
            for (int c = 0; c < 4; c++) {
                aR[c] = *(const float4*)(ap + 4*c);
                bR[c] = *(const float4*)(bp + 4*c);
            }
        }
#pragma unroll 8
        for (int kk = 0; kk < 32; kk++) {
            ulonglong2 ap2 = *(const ulonglong2*)&As_t[kk][ty*4];
            float4 b0 = *(const float4*)&Bs[kk][tx*8];
            float4 b1 = *(const float4*)&Bs[kk][tx*8+4];
            u64 apx[2] = {ap2.x, ap2.y};
            u64 br[8] = {rep2(b0.x),rep2(b0.y),rep2(b0.z),rep2(b0.w),
                         rep2(b1.x),rep2(b1.y),rep2(b1.z),rep2(b1.w)};
#pragma unroll
            for (int i = 0; i < 2; i++)
#pragma unroll
                for (int j = 0; j < 8; j++)
                    fma2(acc[i][j], apx[i], br[j]);
        }
        __syncthreads();
    }

    const int c0 = tx*8;
#pragma unroll
    for (int i = 0; i < 2; i++) {
#pragma unroll
        for (int lane = 0; lane < 2; lane++) {
            int bt = rowBase + ty*4 + 2*i + lane;
            size_t base = (size_t)bt*ND + n*DD + c0;
            float4 x0 = *(const float4*)(g_Xp + base);
            float4 x1 = *(const float4*)(g_Xp + base + 4);
            float4 o0, o1;
            o0.x = gated(x0.x + gcomp(acc[i][0],lane));
            o0.y = gated(x0.y + gcomp(acc[i][1],lane));
            o0.z = gated(x0.z + gcomp(acc[i][2],lane));
            o0.w = gated(x0.w + gcomp(acc[i][3],lane));
            o1.x = gated(x1.x + gcomp(acc[i][4],lane));
            o1.y = gated(x1.y + gcomp(acc[i][5],lane));
            o1.z = gated(x1.z + gcomp(acc[i][6],lane));
            o1.w = gated(x1.w + gcomp(acc[i][7],lane));
            *(float4*)(Hout + base) = o0;
            *(float4*)(Hout + base + 4) = o1;
        }
    }
}

// ---------------- output: [Xp|H1|H2] @ gcnW^T + gcnB -> [B,D,N,T] ----------------
__global__ void __launch_bounds__(128) k_out(const float* __restrict__ gcnB,
                                             float* __restrict__ out) {
    const int b = blockIdx.y;
    const int nBase = blockIdx.x*4;
    __shared__ __align__(16) float Hc[4*12*192];
    const int tid = threadIdx.x;
    float4* Hc4 = (float4*)Hc;
#pragma unroll
    for (int i = 0; i < 18; i++) {
        int lin4 = tid + i*128;
        int nl = lin4 / 576;
        int rem = lin4 - nl*576;
        int t = rem / 48;
        int f4 = rem - t*48;
        int seg = f4 >> 4, fd4 = f4 & 15;
        const float* src = (seg == 0) ? g_Xp : ((seg == 1) ? g_H1 : g_H2);
        Hc4[lin4] = *(const float4*)(src + (size_t)(b*TT+t)*ND + (nBase+nl)*DD + fd4*4);
    }
    __syncthreads();
    const int d2 = tid & 31, nloc = tid >> 5;
    u64 acc[12][2] = {};
    const ulonglong2* WT = (const ulonglong2*)g_gcnWT4;
#pragma unroll 4
    for (int f4 = 0; f4 < 48; f4++) {
        ulonglong2 wA = WT[f4*64 + d2];
        ulonglong2 wB = WT[f4*64 + d2 + 32];
        const float* hb = &Hc[nloc*2304 + f4*4];
#pragma unroll
        for (int t = 0; t < 12; t++) {
            ulonglong2 hp = *(const ulonglong2*)&hb[t*192];
            fma2(acc[t][0], hp.x, wA.x);
            fma2(acc[t][0], hp.y, wA.y);
            fma2(acc[t][1], hp.x, wB.x);
            fma2(acc[t][1], hp.y, wB.y);
        }
    }
    const int n = nBase + nloc;
#pragma unroll
    for (int dsel = 0; dsel < 2; dsel++) {
        int d = d2 + dsel*32;
        float bias = gcnB[d];
        float* op = out + ((size_t)(b*DD+d)*NN + n)*TT;
        float v[12];
#pragma unroll
        for (int t = 0; t < 12; t++) v[t] = lo2(acc[t][dsel]) + hi2(acc[t][dsel]) + bias;
#pragma unroll
        for (int q = 0; q < 3; q++)
            *(float4*)&op[q*4] = make_float4(v[q*4], v[q*4+1], v[q*4+2], v[q*4+3]);
    }
}

// ---------------- launcher ----------------
extern "C" void kernel_launch(void* const* d_in, const int* in_sizes, int n_in,
                              void* d_out, int out_size) {
    const float* X    = (const float*)d_in[0];
    const float* te   = (const float*)d_in[1];
    const float* adjW = (const float*)d_in[2];
    const float* adjB = (const float*)d_in[3];
    const float* tW1  = (const float*)d_in[4];
    const float* tW2  = (const float*)d_in[5];
    const float* a1   = (const float*)d_in[6];
    const float* a2   = (const float*)d_in[7];
    const float* b1   = (const float*)d_in[8];
    const float* b2   = (const float*)d_in[9];
    const float* gcnW = (const float*)d_in[10];
    const float* gcnB = (const float*)d_in[11];
    float* out = (float*)d_out;

    k_SB <<<(NN2 + 255)/256, 256>>>(a1, a2, b1, b2);
    k_Wp <<<(NN*DD*DD + 255)/256, 256>>>(tW1, tW2);
    k_gWT<<<(192*DD + 255)/256, 256>>>(gcnW);
    k_txp<<<dim3(NN, BB), 256>>>(X);

    k_adj<<<dim3(25, BT), 128>>>(te, adjW, adjB);

    // hop 1
    k_mm    <<<dim3(5, BT), 128>>>(0);
    k_nodemm<<<dim3(6, NN), 128>>>(0);
    // hop 2
    k_mm    <<<dim3(5, BT), 128>>>(1);
    k_nodemm<<<dim3(6, NN), 128>>>(1);

    k_out<<<dim3(75, BB), 128>>>(gcnB, out);
}